// round 9
// baseline (speedup 1.0000x reference)
#include <cuda_runtime.h>
#include <cstdint>

#define Tlen 1024
#define NCTA 128
#define NTHR 512

typedef unsigned long long ull;

struct __align__(16) Smem {
    ull   mb[3];           // one mbarrier per hc buffer (count = 4 source CTAs)
    ull   pad_;
    float hc[3][4][196];   // [buf][batch][h1(0..127) ++ h2(128..191)]
    float xs[1024][4];     // staged x, interleaved [t][b]
};
__shared__ Smem sm;

__device__ __forceinline__ float tanha(float x) {
    float y; asm("tanh.approx.f32 %0, %1;" : "=f"(y) : "f"(x)); return y;
}
__device__ __forceinline__ float sigm(float v) { return fmaf(tanha(0.5f * v), 0.5f, 0.5f); }

__device__ __forceinline__ uint32_t s2u(const void* p) {
    uint32_t a;
    asm("{ .reg .u64 t; cvta.to.shared.u64 t, %1; cvt.u32.u64 %0, t; }" : "=r"(a) : "l"(p));
    return a;
}
__device__ __forceinline__ uint32_t mapa_r(uint32_t saddr, int rank) {
    uint32_t r;
    asm volatile("mapa.shared::cluster.u32 %0, %1, %2;" : "=r"(r) : "r"(saddr), "r"(rank));
    return r;
}
__device__ __forceinline__ void st_cl(uint32_t addr, float v) {
    asm volatile("st.shared::cluster.f32 [%0], %1;" :: "r"(addr), "f"(v) : "memory");
}
__device__ __forceinline__ void marr(uint32_t addr) {
    asm volatile("mbarrier.arrive.shared::cluster.b64 _, [%0];" :: "r"(addr) : "memory");
}
__device__ __forceinline__ void fence_cluster() {
    asm volatile("fence.acq_rel.cluster;" ::: "memory");
}
__device__ __forceinline__ void mwait(uint32_t mbar, uint32_t parity) {
    asm volatile(
        "{\n\t.reg .pred P1;\n\t"
        "WAIT_LOOP_%=:\n\t"
        "mbarrier.try_wait.parity.acquire.cta.shared::cta.b64 P1, [%0], %1, 0x989680;\n\t"
        "@P1 bra.uni WAIT_DONE_%=;\n\t"
        "bra.uni WAIT_LOOP_%=;\n\t"
        "WAIT_DONE_%=:\n\t}"
        :: "r"(mbar), "r"(parity) : "memory");
}
__device__ __forceinline__ void csync() {
    asm volatile("barrier.cluster.arrive.aligned;" ::: "memory");
    asm volatile("barrier.cluster.wait.aligned;" ::: "memory");
}
__device__ __forceinline__ void ffma2(ull& acc, ull a, ull b) {
    asm("fma.rn.f32x2 %0, %1, %2, %0;" : "+l"(acc) : "l"(a), "l"(b));
}
__device__ __forceinline__ float2 u2f2(ull u) {
    float2 f;
    asm("mov.b64 {%0, %1}, %2;" : "=f"(f.x), "=f"(f.y) : "l"(u));
    return f;
}
__device__ __forceinline__ ull pk(float lo, float hi) {
    ull r;
    asm("mov.b64 %0, {%1, %2};" : "=l"(r) : "f"(lo), "f"(hi));
    return r;
}

// 4x4 gate<->batch transpose across lane bits [0:1]; lane G: in s[b]=M[G][b],
// out s[j]=M[j][G].
__device__ __forceinline__ void transpose4(float s[4], int G) {
    const unsigned FULL = 0xffffffffu;
    int g0 = G & 1, g1 = (G >> 1) & 1;
    float x0 = g0 ? s[0] : s[1];
    float x1 = g0 ? s[2] : s[3];
    float y0 = __shfl_xor_sync(FULL, x0, 1);
    float y1 = __shfl_xor_sync(FULL, x1, 1);
    if (g0) { s[0] = y0; s[2] = y1; } else { s[1] = y0; s[3] = y1; }
    x0 = g1 ? s[0] : s[2];
    x1 = g1 ? s[1] : s[3];
    y0 = __shfl_xor_sync(FULL, x0, 2);
    y1 = __shfl_xor_sync(FULL, x1, 2);
    if (g1) { s[0] = y0; s[1] = y1; } else { s[2] = y0; s[3] = y1; }
}

#define HC_BUF_BYTES (4 * 196 * 4)

__global__ void __launch_bounds__(NTHR, 1) __cluster_dims__(4, 1, 1)
lstm_cluster_kernel(
    const float* __restrict__ x,
    const float* __restrict__ w_ih1,  // [512][1]
    const float* __restrict__ w_hh1,  // [512][128]
    const float* __restrict__ b_ih1,
    const float* __restrict__ b_hh1,
    const float* __restrict__ w_ih2,  // [256][128]
    const float* __restrict__ w_hh2,  // [256][64]
    const float* __restrict__ b_ih2,
    const float* __restrict__ b_hh2,
    float* __restrict__ out)          // [128][64]
{
    const int tid  = threadIdx.x;
    const int lane = tid & 31;
    const int wrp  = tid >> 5;        // 16 warps
    const int q    = blockIdx.x & 3;
    const int cid  = blockIdx.x >> 2;

    // lane = g(2b) | ks(3b);  warp -> dim
    const int g  = lane & 3;
    const int ks = lane >> 2;         // 0..7 k-slice
    const int dl = wrp;               // L1: rows dl, dl+16 (of 32); L2: row dl (of 16)
    const int rowsel = (ks >= 4);     // L1: which row this lane finalizes/stores

    // ---------------- weights -> registers (k-striped eighths) ----------------
    // L1: rows r0 = g*128+32q+dl, r1 = r0+16 ; k in {ks*4 + 32*kk + e}, kk=0..3
    ulonglong2 w1a[4], w1b[4];
    {
        const int r0 = g * 128 + 32 * q + dl;
        const float* p0 = w_hh1 + r0 * 128 + ks * 4;
        const float* p1 = w_hh1 + (r0 + 16) * 128 + ks * 4;
#pragma unroll
        for (int kk = 0; kk < 4; kk++) {
            float4 f0 = *reinterpret_cast<const float4*>(p0 + kk * 32);
            float4 f1 = *reinterpret_cast<const float4*>(p1 + kk * 32);
            w1a[kk].x = pk(f0.x, f0.y); w1a[kk].y = pk(f0.z, f0.w);
            w1b[kk].x = pk(f1.x, f1.y); w1b[kk].y = pk(f1.z, f1.w);
        }
    }
    // L2: row r2 = g*64+16q+dl ; k in {ks*4 + 32*kk + e}, kk=0..5 over [w_ih2|w_hh2]
    ulonglong2 w2[6];
    {
        const int r2 = g * 64 + 16 * q + dl;
#pragma unroll
        for (int kk = 0; kk < 6; kk++) {
            int k0 = ks * 4 + kk * 32;
            float f[4];
#pragma unroll
            for (int e = 0; e < 4; e++) {
                int k = k0 + e;
                f[e] = (k < 128) ? w_ih2[r2 * 128 + k] : w_hh2[r2 * 64 + (k - 128)];
            }
            w2[kk].x = pk(f[0], f[1]);
            w2[kk].y = pk(f[2], f[3]);
        }
    }

    // cell constants for this lane's selected L1 row + L2 row
    float wih1s[4], b1s[4], b2c[4];
#pragma unroll
    for (int j = 0; j < 4; j++) {
        int ra = j * 128 + 32 * q + dl + (rowsel ? 16 : 0);
        wih1s[j] = w_ih1[ra];
        b1s[j]   = b_ih1[ra] + b_hh1[ra];
        int rb = j * 64 + 16 * q + dl;
        b2c[j]   = b_ih2[rb] + b_hh2[rb];
    }

    // ---------------- init smem ----------------
    for (int idx = tid; idx < 4 * 1024; idx += NTHR) {
        int b = idx >> 10, t = idx & 1023;
        sm.xs[t][b] = x[(4 * cid + b) * 1024 + t];
    }
    for (int idx = tid; idx < 3 * 4 * 196; idx += NTHR)
        (&sm.hc[0][0][0])[idx] = 0.0f;
    if (tid == 0) {
#pragma unroll
        for (int j = 0; j < 3; j++) {
            uint32_t a = s2u(&sm.mb[j]);
            asm volatile("mbarrier.init.shared.b64 [%0], 4;" :: "r"(a) : "memory");
        }
    }

    // ---------------- cluster address constants ----------------
    const uint32_t base0 = s2u(&sm);
    const uint32_t m0    = mapa_r(base0, 0);
    uint32_t dd[4];
    dd[0] = 0;
    dd[1] = mapa_r(base0, 1) - m0;
    dd[2] = mapa_r(base0, 2) - m0;
    dd[3] = mapa_r(base0, 3) - m0;
    const uint32_t HCO = s2u(&sm.hc[0][0][0]) - base0;
    const uint32_t MBO = s2u(&sm.mb[0]) - base0;
    const uint32_t rk  = m0 + dd[ks & 3];   // this lane's scatter destination rank

    csync();  // mbars + zeroed smem visible cluster-wide

    float c1 = 0.0f, c2 = 0.0f;
    const unsigned FULL = 0xffffffffu;

    for (int i = 0; i <= Tlen; i++) {
        const int bufW = i % 3;
        int bufR = 2;                 // zeroed buffer for i==0
        if (i >= 1) {
            const int im1 = i - 1;
            bufR = im1 % 3;
            mwait(base0 + MBO + bufR * 8, (uint32_t)((im1 / 3) & 1));
        }

        // ======== L1 (step i): dual-row dot, k-eighth ========
        if (i < Tlen) {
            float s0[4], s1[4];
#pragma unroll
            for (int b = 0; b < 4; b++) {
                const ulonglong2* hp =
                    reinterpret_cast<const ulonglong2*>(&sm.hc[bufR][b][0]);
                ull a00 = 0ull, a01 = 0ull, a10 = 0ull, a11 = 0ull;
#pragma unroll
                for (int kk = 0; kk < 4; kk++) {
                    ulonglong2 h = hp[ks + 8 * kk];
                    ffma2(a00, h.x, w1a[kk].x);
                    ffma2(a01, h.y, w1a[kk].y);
                    ffma2(a10, h.x, w1b[kk].x);
                    ffma2(a11, h.y, w1b[kk].y);
                }
                float2 f0 = u2f2(a00), f1 = u2f2(a01);
                float2 f2 = u2f2(a10), f3 = u2f2(a11);
                s0[b] = (f0.x + f0.y) + (f1.x + f1.y);
                s1[b] = (f2.x + f2.y) + (f3.x + f3.y);
            }
            // allreduce over ks (lane bits 2,3,4), both rows
#pragma unroll
            for (int b = 0; b < 4; b++) {
                s0[b] += __shfl_xor_sync(FULL, s0[b], 4);
                s1[b] += __shfl_xor_sync(FULL, s1[b], 4);
                s0[b] += __shfl_xor_sync(FULL, s0[b], 8);
                s1[b] += __shfl_xor_sync(FULL, s1[b], 8);
                s0[b] += __shfl_xor_sync(FULL, s0[b], 16);
                s1[b] += __shfl_xor_sync(FULL, s1[b], 16);
            }
            // each lane finalizes ONE row (a if ks<4 else b)
            float sel[4];
#pragma unroll
            for (int b = 0; b < 4; b++) sel[b] = rowsel ? s1[b] : s0[b];
            transpose4(sel, g);       // sel[j] = gate-j preact, batch beta=g
            const int beta = g;
            float xv = sm.xs[i][beta];
            float ai = fmaf(xv, wih1s[0], sel[0] + b1s[0]);
            float af = fmaf(xv, wih1s[1], sel[1] + b1s[1]);
            float ag = fmaf(xv, wih1s[2], sel[2] + b1s[2]);
            float ao = fmaf(xv, wih1s[3], sel[3] + b1s[3]);
            c1 = sigm(af) * c1 + sigm(ai) * tanha(ag);
            float h = sigm(ao) * tanha(c1);
            int dv = dl + (rowsel ? 16 : 0);
            st_cl(rk + HCO + bufW * HC_BUF_BYTES + (beta * 196 + 32 * q + dv) * 4, h);
        }

        // ======== L2 (step i-1): single-row dot, k-eighth ========
        {
            float h2v = 0.0f;
            if (i >= 1) {
                float s[4];
#pragma unroll
                for (int b = 0; b < 4; b++) {
                    const ulonglong2* hp =
                        reinterpret_cast<const ulonglong2*>(&sm.hc[bufR][b][0]);
                    ull a0 = 0ull, a1 = 0ull;
#pragma unroll
                    for (int kk = 0; kk < 6; kk++) {
                        ulonglong2 h = hp[ks + 8 * kk];
                        ffma2(a0, h.x, w2[kk].x);
                        ffma2(a1, h.y, w2[kk].y);
                    }
                    float2 f0 = u2f2(a0), f1 = u2f2(a1);
                    s[b] = (f0.x + f0.y) + (f1.x + f1.y);
                }
#pragma unroll
                for (int b = 0; b < 4; b++) {
                    s[b] += __shfl_xor_sync(FULL, s[b], 4);
                    s[b] += __shfl_xor_sync(FULL, s[b], 8);
                    s[b] += __shfl_xor_sync(FULL, s[b], 16);
                }
                transpose4(s, g);
                float ai = s[0] + b2c[0];
                float af = s[1] + b2c[1];
                float ag = s[2] + b2c[2];
                float ao = s[3] + b2c[3];
                c2 = sigm(af) * c2 + sigm(ai) * tanha(ag);
                h2v = sigm(ao) * tanha(c2);
            }
            const int beta = g;
            if (i == Tlen) {
                if (ks == 0) out[(4 * cid + beta) * 64 + 16 * q + dl] = h2v;
            } else if (ks < 4) {
                st_cl(rk + HCO + bufW * HC_BUF_BYTES + (beta * 196 + 128 + 16 * q + dl) * 4,
                      h2v);
            }
        }

        // ======== publish step i's buffer ========
        if (i < Tlen) {
            __syncthreads();
            if (tid == 0) {
                fence_cluster();
                uint32_t am = m0 + MBO + bufW * 8;
                marr(am); marr(am + dd[1]); marr(am + dd[2]); marr(am + dd[3]);
            }
        }
    }

    csync();  // keep smem alive for peers
}

extern "C" void kernel_launch(void* const* d_in, const int* in_sizes, int n_in,
                              void* d_out, int out_size) {
    const float* x     = (const float*)d_in[0];
    const float* w_ih1 = (const float*)d_in[1];
    const float* w_hh1 = (const float*)d_in[2];
    const float* b_ih1 = (const float*)d_in[3];
    const float* b_hh1 = (const float*)d_in[4];
    const float* w_ih2 = (const float*)d_in[5];
    const float* w_hh2 = (const float*)d_in[6];
    const float* b_ih2 = (const float*)d_in[7];
    const float* b_hh2 = (const float*)d_in[8];
    float* out = (float*)d_out;

    lstm_cluster_kernel<<<NCTA, NTHR>>>(
        x, w_ih1, w_hh1, b_ih1, b_hh1, w_ih2, w_hh2, b_ih2, b_hh2, out);
    (void)in_sizes; (void)n_in; (void)out_size;
}

// round 10
// speedup vs baseline: 1.0647x; 1.0647x over previous
#include <cuda_runtime.h>
#include <cstdint>

#define Tlen 1024
#define NCTA 128
#define NTHR 512

typedef unsigned long long ull;

struct __align__(16) Smem {
    ull   mb[3];           // one mbarrier per hc buffer (count = 4 source CTAs)
    ull   pad_;
    float hc[3][4][196];   // [buf][batch][h1(0..127) ++ h2(128..191)]
    float xs[1024][4];     // staged x, interleaved [t][b]
};
__shared__ Smem sm;

__device__ __forceinline__ float tanha(float x) {
    float y; asm("tanh.approx.f32 %0, %1;" : "=f"(y) : "f"(x)); return y;
}
__device__ __forceinline__ float sigm(float v) { return fmaf(tanha(0.5f * v), 0.5f, 0.5f); }

__device__ __forceinline__ uint32_t s2u(const void* p) {
    uint32_t a;
    asm("{ .reg .u64 t; cvta.to.shared.u64 t, %1; cvt.u32.u64 %0, t; }" : "=r"(a) : "l"(p));
    return a;
}
__device__ __forceinline__ uint32_t mapa_r(uint32_t saddr, int rank) {
    uint32_t r;
    asm volatile("mapa.shared::cluster.u32 %0, %1, %2;" : "=r"(r) : "r"(saddr), "r"(rank));
    return r;
}
__device__ __forceinline__ void st_cl(uint32_t addr, float v) {
    asm volatile("st.shared::cluster.f32 [%0], %1;" :: "r"(addr), "f"(v) : "memory");
}
__device__ __forceinline__ void marr(uint32_t addr) {
    asm volatile("mbarrier.arrive.shared::cluster.b64 _, [%0];" :: "r"(addr) : "memory");
}
__device__ __forceinline__ void fence_cluster() {
    asm volatile("fence.acq_rel.cluster;" ::: "memory");
}
__device__ __forceinline__ void mwait(uint32_t mbar, uint32_t parity) {
    asm volatile(
        "{\n\t.reg .pred P1;\n\t"
        "WAIT_LOOP_%=:\n\t"
        "mbarrier.try_wait.parity.acquire.cta.shared::cta.b64 P1, [%0], %1, 0x989680;\n\t"
        "@P1 bra.uni WAIT_DONE_%=;\n\t"
        "bra.uni WAIT_LOOP_%=;\n\t"
        "WAIT_DONE_%=:\n\t}"
        :: "r"(mbar), "r"(parity) : "memory");
}
__device__ __forceinline__ void csync() {
    asm volatile("barrier.cluster.arrive.aligned;" ::: "memory");
    asm volatile("barrier.cluster.wait.aligned;" ::: "memory");
}
__device__ __forceinline__ void ffma2(ull& acc, ull a, ull b) {
    asm("fma.rn.f32x2 %0, %1, %2, %0;" : "+l"(acc) : "l"(a), "l"(b));
}
__device__ __forceinline__ float2 u2f2(ull u) {
    float2 f;
    asm("mov.b64 {%0, %1}, %2;" : "=f"(f.x), "=f"(f.y) : "l"(u));
    return f;
}
__device__ __forceinline__ ull pk(float lo, float hi) {
    ull r;
    asm("mov.b64 %0, {%1, %2};" : "=l"(r) : "f"(lo), "f"(hi));
    return r;
}

// 4x4 gate<->batch transpose across lane bits [0:1]; lane G: in s[b]=M[G][b],
// out s[j]=M[j][G].
__device__ __forceinline__ void transpose4(float s[4], int G) {
    const unsigned FULL = 0xffffffffu;
    int g0 = G & 1, g1 = (G >> 1) & 1;
    float x0 = g0 ? s[0] : s[1];
    float x1 = g0 ? s[2] : s[3];
    float y0 = __shfl_xor_sync(FULL, x0, 1);
    float y1 = __shfl_xor_sync(FULL, x1, 1);
    if (g0) { s[0] = y0; s[2] = y1; } else { s[1] = y0; s[3] = y1; }
    x0 = g1 ? s[0] : s[2];
    x1 = g1 ? s[1] : s[3];
    y0 = __shfl_xor_sync(FULL, x0, 2);
    y1 = __shfl_xor_sync(FULL, x1, 2);
    if (g1) { s[0] = y0; s[1] = y1; } else { s[2] = y0; s[3] = y1; }
}

#define HC_BUF_BYTES (4 * 196 * 4)

__global__ void __launch_bounds__(NTHR, 1) __cluster_dims__(4, 1, 1)
lstm_cluster_kernel(
    const float* __restrict__ x,
    const float* __restrict__ w_ih1,  // [512][1]
    const float* __restrict__ w_hh1,  // [512][128]
    const float* __restrict__ b_ih1,
    const float* __restrict__ b_hh1,
    const float* __restrict__ w_ih2,  // [256][128]
    const float* __restrict__ w_hh2,  // [256][64]
    const float* __restrict__ b_ih2,
    const float* __restrict__ b_hh2,
    float* __restrict__ out)          // [128][64]
{
    const int tid  = threadIdx.x;
    const int lane = tid & 31;
    const int wrp  = tid >> 5;        // 16 warps: 0-7 = L1, 8-15 = L2
    const int q    = blockIdx.x & 3;
    const int cid  = blockIdx.x >> 2;

    const bool isL1 = (wrp < 8);
    const int g = lane & 3;           // gate (also batch after transpose)

    // L1 roles (warps 0-7): lane = g(2b) | kh(1b) | dlb(2b); dim dl = wrp*4+dlb
    const int kh  = (lane >> 2) & 1;
    const int dlb = (lane >> 3) & 3;
    const int dl  = wrp * 4 + dlb;    // 0..31
    // L2 roles (warps 8-15): lane = g(2b) | kq(2b) | dlb2(1b); dim dl2 = (wrp-8)*2+dlb2
    const int kq   = (lane >> 2) & 3;
    const int dlb2 = (lane >> 4) & 1;
    const int dl2  = (wrp - 8) * 2 + dlb2;  // 0..15

    // ---------------- weights -> registers ----------------
    // L1 thread: row (g, dl), k in {kh*4 + 8*j + e}, j=0..15 -> 64 floats
    ull w1[32];
    // L2 thread: row (g, dl2), k in {kq*4 + 16*j + e}, j=0..11 over concat -> 48 floats
    ull w2[24];
    if (isL1) {
        const int r = g * 128 + 32 * q + dl;
        const float* p = w_hh1 + r * 128 + kh * 4;
#pragma unroll
        for (int j = 0; j < 16; j++) {
            float4 f = *reinterpret_cast<const float4*>(p + j * 8);
            w1[2 * j]     = pk(f.x, f.y);
            w1[2 * j + 1] = pk(f.z, f.w);
        }
    } else {
        const int r = g * 64 + 16 * q + dl2;
#pragma unroll
        for (int j = 0; j < 12; j++) {
            int k0 = kq * 4 + 16 * j;   // 4-float chunk, never straddles 128
            float4 f;
            if (k0 < 128) f = *reinterpret_cast<const float4*>(w_ih2 + r * 128 + k0);
            else          f = *reinterpret_cast<const float4*>(w_hh2 + r * 64 + (k0 - 128));
            w2[2 * j]     = pk(f.x, f.y);
            w2[2 * j + 1] = pk(f.z, f.w);
        }
    }

    // cell constants
    float wih1s[4], b1s[4], b2c[4];
    if (isL1) {
#pragma unroll
        for (int j = 0; j < 4; j++) {
            int r = j * 128 + 32 * q + dl;
            wih1s[j] = w_ih1[r];
            b1s[j]   = b_ih1[r] + b_hh1[r];
        }
    } else {
#pragma unroll
        for (int j = 0; j < 4; j++) {
            int r = j * 64 + 16 * q + dl2;
            b2c[j] = b_ih2[r] + b_hh2[r];
        }
    }

    // ---------------- init smem ----------------
    for (int idx = tid; idx < 4 * 1024; idx += NTHR) {
        int b = idx >> 10, t = idx & 1023;
        sm.xs[t][b] = x[(4 * cid + b) * 1024 + t];
    }
    for (int idx = tid; idx < 3 * 4 * 196; idx += NTHR)
        (&sm.hc[0][0][0])[idx] = 0.0f;
    if (tid == 0) {
#pragma unroll
        for (int j = 0; j < 3; j++) {
            uint32_t a = s2u(&sm.mb[j]);
            asm volatile("mbarrier.init.shared.b64 [%0], 4;" :: "r"(a) : "memory");
        }
    }

    // ---------------- cluster address constants ----------------
    const uint32_t base0 = s2u(&sm);
    const uint32_t m0    = mapa_r(base0, 0);
    uint32_t dd[4];
    dd[0] = 0;
    dd[1] = mapa_r(base0, 1) - m0;
    dd[2] = mapa_r(base0, 2) - m0;
    dd[3] = mapa_r(base0, 3) - m0;
    const uint32_t HCO = s2u(&sm.hc[0][0][0]) - base0;
    const uint32_t MBO = s2u(&sm.mb[0]) - base0;
    // L1: lane kh covers ranks {2kh, 2kh+1}; L2: lane kq covers rank kq
    const uint32_t rkA = m0 + dd[2 * kh];
    const uint32_t rkB = m0 + dd[2 * kh + 1];
    const uint32_t rkQ = m0 + dd[kq];

    csync();  // mbars + zeroed smem visible cluster-wide

    float c1 = 0.0f, c2 = 0.0f;
    const unsigned FULL = 0xffffffffu;

    for (int i = 0; i <= Tlen; i++) {
        const int bufW = i % 3;
        int bufR = 2;                 // zeroed buffer for i==0
        if (i >= 1) {
            const int im1 = i - 1;
            bufR = im1 % 3;
            mwait(base0 + MBO + bufR * 8, (uint32_t)((im1 / 3) & 1));
        }

        if (isL1) {
            // ======== L1 (step i): full-row half-k dot, batch in-thread ========
            if (i < Tlen) {
                float s[4];
#pragma unroll
                for (int b = 0; b < 4; b++) {
                    const ulonglong2* hp = reinterpret_cast<const ulonglong2*>(
                        &sm.hc[bufR][b][kh * 4]);
                    ull a0 = 0ull, a1 = 0ull;
#pragma unroll
                    for (int j = 0; j < 16; j++) {
                        ulonglong2 h = hp[2 * j];   // floats kh*4+8j .. +3
                        ffma2(a0, h.x, w1[2 * j]);
                        ffma2(a1, h.y, w1[2 * j + 1]);
                    }
                    float2 f0 = u2f2(a0), f1 = u2f2(a1);
                    s[b] = (f0.x + f0.y) + (f1.x + f1.y);
                }
                // reduce over kh (lane bit 2)
#pragma unroll
                for (int b = 0; b < 4; b++) s[b] += __shfl_xor_sync(FULL, s[b], 4);
                transpose4(s, g);     // s[j] = gate-j preact, batch beta=g
                const int beta = g;
                float xv = sm.xs[i][beta];
                float ai = fmaf(xv, wih1s[0], s[0] + b1s[0]);
                float af = fmaf(xv, wih1s[1], s[1] + b1s[1]);
                float ag = fmaf(xv, wih1s[2], s[2] + b1s[2]);
                float ao = fmaf(xv, wih1s[3], s[3] + b1s[3]);
                c1 = sigm(af) * c1 + sigm(ai) * tanha(ag);
                float h = sigm(ao) * tanha(c1);
                uint32_t off = HCO + bufW * HC_BUF_BYTES + (beta * 196 + 32 * q + dl) * 4;
                st_cl(rkA + off, h);
                st_cl(rkB + off, h);
            }
        } else {
            // ======== L2 (step i-1): full-row quarter-k dot over [h1 ++ h2] ========
            float h2v = 0.0f;
            if (i >= 1) {
                float s[4];
#pragma unroll
                for (int b = 0; b < 4; b++) {
                    const ulonglong2* hp = reinterpret_cast<const ulonglong2*>(
                        &sm.hc[bufR][b][kq * 4]);
                    ull a0 = 0ull, a1 = 0ull;
#pragma unroll
                    for (int j = 0; j < 12; j++) {
                        ulonglong2 h = hp[4 * j];   // floats kq*4+16j .. +3
                        ffma2(a0, h.x, w2[2 * j]);
                        ffma2(a1, h.y, w2[2 * j + 1]);
                    }
                    float2 f0 = u2f2(a0), f1 = u2f2(a1);
                    s[b] = (f0.x + f0.y) + (f1.x + f1.y);
                }
                // reduce over kq (lane bits 2,3)
#pragma unroll
                for (int b = 0; b < 4; b++) {
                    s[b] += __shfl_xor_sync(FULL, s[b], 4);
                    s[b] += __shfl_xor_sync(FULL, s[b], 8);
                }
                transpose4(s, g);
                float ai = s[0] + b2c[0];
                float af = s[1] + b2c[1];
                float ag = s[2] + b2c[2];
                float ao = s[3] + b2c[3];
                c2 = sigm(af) * c2 + sigm(ai) * tanha(ag);
                h2v = sigm(ao) * tanha(c2);
            }
            const int beta = g;
            if (i == Tlen) {
                if (kq == 0) out[(4 * cid + beta) * 64 + 16 * q + dl2] = h2v;
            } else {
                st_cl(rkQ + HCO + bufW * HC_BUF_BYTES +
                      (beta * 196 + 128 + 16 * q + dl2) * 4, h2v);
            }
        }

        // ======== publish step i's buffer ========
        if (i < Tlen) {
            __syncthreads();
            if (tid == 0) {
                fence_cluster();
                uint32_t am = m0 + MBO + bufW * 8;
                marr(am); marr(am + dd[1]); marr(am + dd[2]); marr(am + dd[3]);
            }
        }
    }

    csync();  // keep smem alive for peers
}

extern "C" void kernel_launch(void* const* d_in, const int* in_sizes, int n_in,
                              void* d_out, int out_size) {
    const float* x     = (const float*)d_in[0];
    const float* w_ih1 = (const float*)d_in[1];
    const float* w_hh1 = (const float*)d_in[2];
    const float* b_ih1 = (const float*)d_in[3];
    const float* b_hh1 = (const float*)d_in[4];
    const float* w_ih2 = (const float*)d_in[5];
    const float* w_hh2 = (const float*)d_in[6];
    const float* b_ih2 = (const float*)d_in[7];
    const float* b_hh2 = (const float*)d_in[8];
    float* out = (float*)d_out;

    lstm_cluster_kernel<<<NCTA, NTHR>>>(
        x, w_ih1, w_hh1, b_ih1, b_hh1, w_ih2, w_hh2, b_ih2, b_hh2, out);
    (void)in_sizes; (void)n_in; (void)out_size;
}

// round 11
// speedup vs baseline: 1.0870x; 1.0210x over previous
#include <cuda_runtime.h>
#include <cstdint>

#define Tlen 1024
#define NCTA 128
#define NTHR 512

typedef unsigned long long ull;

struct __align__(16) Smem {
    ull   mb[3];           // one mbarrier per hc buffer (count = 64 = 16 warps x 4 CTAs)
    ull   pad_;
    float hc[3][4][196];   // [buf][batch][h1(0..127) ++ h2(128..191)]
    float xs[1024][4];     // staged x, interleaved [t][b]
};
__shared__ Smem sm;

__device__ __forceinline__ float tanha(float x) {
    float y; asm("tanh.approx.f32 %0, %1;" : "=f"(y) : "f"(x)); return y;
}
__device__ __forceinline__ float sigm(float v) { return fmaf(tanha(0.5f * v), 0.5f, 0.5f); }

__device__ __forceinline__ uint32_t s2u(const void* p) {
    uint32_t a;
    asm("{ .reg .u64 t; cvta.to.shared.u64 t, %1; cvt.u32.u64 %0, t; }" : "=r"(a) : "l"(p));
    return a;
}
__device__ __forceinline__ uint32_t mapa_r(uint32_t saddr, int rank) {
    uint32_t r;
    asm volatile("mapa.shared::cluster.u32 %0, %1, %2;" : "=r"(r) : "r"(saddr), "r"(rank));
    return r;
}
__device__ __forceinline__ void st_cl(uint32_t addr, float v) {
    asm volatile("st.shared::cluster.f32 [%0], %1;" :: "r"(addr), "f"(v) : "memory");
}
__device__ __forceinline__ void marr(uint32_t addr) {
    asm volatile("mbarrier.arrive.shared::cluster.b64 _, [%0];" :: "r"(addr) : "memory");
}
__device__ __forceinline__ void fence_cluster() {
    asm volatile("fence.acq_rel.cluster;" ::: "memory");
}
__device__ __forceinline__ void mwait(uint32_t mbar, uint32_t parity) {
    asm volatile(
        "{\n\t.reg .pred P1;\n\t"
        "WAIT_LOOP_%=:\n\t"
        "mbarrier.try_wait.parity.acquire.cta.shared::cta.b64 P1, [%0], %1, 0x989680;\n\t"
        "@P1 bra.uni WAIT_DONE_%=;\n\t"
        "bra.uni WAIT_LOOP_%=;\n\t"
        "WAIT_DONE_%=:\n\t}"
        :: "r"(mbar), "r"(parity) : "memory");
}
__device__ __forceinline__ void csync() {
    asm volatile("barrier.cluster.arrive.aligned;" ::: "memory");
    asm volatile("barrier.cluster.wait.aligned;" ::: "memory");
}
__device__ __forceinline__ void ffma2(ull& acc, ull a, ull b) {
    asm("fma.rn.f32x2 %0, %1, %2, %0;" : "+l"(acc) : "l"(a), "l"(b));
}
__device__ __forceinline__ float2 u2f2(ull u) {
    float2 f;
    asm("mov.b64 {%0, %1}, %2;" : "=f"(f.x), "=f"(f.y) : "l"(u));
    return f;
}
__device__ __forceinline__ ull pk(float lo, float hi) {
    ull r;
    asm("mov.b64 %0, {%1, %2};" : "=l"(r) : "f"(lo), "f"(hi));
    return r;
}

// 4x4 gate<->batch transpose across lane bits [0:1]; lane G: in s[b]=M[G][b],
// out s[j]=M[j][G].
__device__ __forceinline__ void transpose4(float s[4], int G) {
    const unsigned FULL = 0xffffffffu;
    int g0 = G & 1, g1 = (G >> 1) & 1;
    float x0 = g0 ? s[0] : s[1];
    float x1 = g0 ? s[2] : s[3];
    float y0 = __shfl_xor_sync(FULL, x0, 1);
    float y1 = __shfl_xor_sync(FULL, x1, 1);
    if (g0) { s[0] = y0; s[2] = y1; } else { s[1] = y0; s[3] = y1; }
    x0 = g1 ? s[0] : s[2];
    x1 = g1 ? s[1] : s[3];
    y0 = __shfl_xor_sync(FULL, x0, 2);
    y1 = __shfl_xor_sync(FULL, x1, 2);
    if (g1) { s[0] = y0; s[1] = y1; } else { s[2] = y0; s[3] = y1; }
}

#define HC_BUF_BYTES (4 * 196 * 4)

__global__ void __launch_bounds__(NTHR, 1) __cluster_dims__(4, 1, 1)
lstm_cluster_kernel(
    const float* __restrict__ x,
    const float* __restrict__ w_ih1,  // [512][1]
    const float* __restrict__ w_hh1,  // [512][128]
    const float* __restrict__ b_ih1,
    const float* __restrict__ b_hh1,
    const float* __restrict__ w_ih2,  // [256][128]
    const float* __restrict__ w_hh2,  // [256][64]
    const float* __restrict__ b_ih2,
    const float* __restrict__ b_hh2,
    float* __restrict__ out)          // [128][64]
{
    const int tid  = threadIdx.x;
    const int lane = tid & 31;
    const int wrp  = tid >> 5;        // 16 warps: 0-7 = L1, 8-15 = L2
    const int q    = blockIdx.x & 3;
    const int cid  = blockIdx.x >> 2;
    const int g    = lane & 3;        // gate (batch after transpose)

    // ---------------- init smem ----------------
    for (int idx = tid; idx < 4 * 1024; idx += NTHR) {
        int b = idx >> 10, t = idx & 1023;
        sm.xs[t][b] = x[(4 * cid + b) * 1024 + t];
    }
    for (int idx = tid; idx < 3 * 4 * 196; idx += NTHR)
        (&sm.hc[0][0][0])[idx] = 0.0f;
    if (tid == 0) {
#pragma unroll
        for (int j = 0; j < 3; j++) {
            uint32_t a = s2u(&sm.mb[j]);
            asm volatile("mbarrier.init.shared.b64 [%0], 64;" :: "r"(a) : "memory");
        }
    }

    // ---------------- cluster address constants ----------------
    const uint32_t base0 = s2u(&sm);
    const uint32_t m0    = mapa_r(base0, 0);
    uint32_t dd[4];
    dd[0] = 0;
    dd[1] = mapa_r(base0, 1) - m0;
    dd[2] = mapa_r(base0, 2) - m0;
    dd[3] = mapa_r(base0, 3) - m0;
    const uint32_t HCO = s2u(&sm.hc[0][0][0]) - base0;
    const uint32_t MBO = s2u(&sm.mb[0]) - base0;

    csync();  // mbars + zeroed smem + xs visible cluster-wide

    const unsigned FULL = 0xffffffffu;

    if (wrp < 8) {
        // ================= L1 warps: steps 0..Tlen-1 =================
        // lane = g(2b) | kq(2b) | dlb(1b); rows (g, dl), (g, dl+16), k-quarter kq
        const int kq  = (lane >> 2) & 3;
        const int dlb = (lane >> 4) & 1;
        const int dl  = wrp * 2 + dlb;        // 0..15
        const int rsel = (kq >= 2);           // which row this lane finalizes
        // weights: k in {kq*4 + 16*j + e}, j=0..7 for both rows
        ull w1a[16], w1b[16];
        {
            const int ra = g * 128 + 32 * q + dl;
            const float* pa = w_hh1 + ra * 128 + kq * 4;
            const float* pb = w_hh1 + (ra + 16) * 128 + kq * 4;
#pragma unroll
            for (int j = 0; j < 8; j++) {
                float4 fa = *reinterpret_cast<const float4*>(pa + j * 16);
                float4 fb = *reinterpret_cast<const float4*>(pb + j * 16);
                w1a[2 * j] = pk(fa.x, fa.y); w1a[2 * j + 1] = pk(fa.z, fa.w);
                w1b[2 * j] = pk(fb.x, fb.y); w1b[2 * j + 1] = pk(fb.z, fb.w);
            }
        }
        float wih1s[4], b1s[4];
#pragma unroll
        for (int j = 0; j < 4; j++) {
            int r = j * 128 + 32 * q + dl + (rsel ? 16 : 0);
            wih1s[j] = w_ih1[r];
            b1s[j]   = b_ih1[r] + b_hh1[r];
        }
        const int dv = dl + (rsel ? 16 : 0);
        const int rep = kq & 1;               // replica -> ranks {2rep, 2rep+1}
        const uint32_t rA = m0 + dd[2 * rep];
        const uint32_t rB = m0 + dd[2 * rep + 1];

        float c1 = 0.0f;
        int wW = 0, rR = 0, ph = 0;
        for (int i = 0; i < Tlen; i++) {
            int bufR;
            if (i == 0) bufR = 2;
            else {
                mwait(base0 + MBO + rR * 8, (uint32_t)ph);
                bufR = rR;
                if (++rR == 3) { rR = 0; ph ^= 1; }
            }
            float s0[4], s1[4];
#pragma unroll
            for (int b = 0; b < 4; b++) {
                const ulonglong2* hp =
                    reinterpret_cast<const ulonglong2*>(&sm.hc[bufR][b][0]);
                ull a0 = 0ull, a1 = 0ull, b0 = 0ull, b1 = 0ull;
#pragma unroll
                for (int j = 0; j < 8; j++) {
                    ulonglong2 h = hp[kq + 4 * j];   // 4 distinct addrs/warp
                    ffma2(a0, h.x, w1a[2 * j]);
                    ffma2(a1, h.y, w1a[2 * j + 1]);
                    ffma2(b0, h.x, w1b[2 * j]);
                    ffma2(b1, h.y, w1b[2 * j + 1]);
                }
                float2 f0 = u2f2(a0), f1 = u2f2(a1);
                float2 f2 = u2f2(b0), f3 = u2f2(b1);
                s0[b] = (f0.x + f0.y) + (f1.x + f1.y);
                s1[b] = (f2.x + f2.y) + (f3.x + f3.y);
            }
#pragma unroll
            for (int b = 0; b < 4; b++) {
                s0[b] += __shfl_xor_sync(FULL, s0[b], 4);
                s1[b] += __shfl_xor_sync(FULL, s1[b], 4);
                s0[b] += __shfl_xor_sync(FULL, s0[b], 8);
                s1[b] += __shfl_xor_sync(FULL, s1[b], 8);
            }
            float sel[4];
#pragma unroll
            for (int b = 0; b < 4; b++) sel[b] = rsel ? s1[b] : s0[b];
            transpose4(sel, g);
            const int beta = g;
            float xv = sm.xs[i][beta];
            float ai = fmaf(xv, wih1s[0], sel[0] + b1s[0]);
            float af = fmaf(xv, wih1s[1], sel[1] + b1s[1]);
            float ag = fmaf(xv, wih1s[2], sel[2] + b1s[2]);
            float ao = fmaf(xv, wih1s[3], sel[3] + b1s[3]);
            c1 = sigm(af) * c1 + sigm(ai) * tanha(ag);
            float h = sigm(ao) * tanha(c1);
            uint32_t off = HCO + wW * HC_BUF_BYTES + (beta * 196 + 32 * q + dv) * 4;
            st_cl(rA + off, h);
            st_cl(rB + off, h);
            __syncwarp();
            if (lane == 0) {
                fence_cluster();
                uint32_t am = m0 + MBO + wW * 8;
                marr(am); marr(am + dd[1]); marr(am + dd[2]); marr(am + dd[3]);
            }
            if (++wW == 3) wW = 0;
        }
    } else {
        // ================= L2 warps: steps 0..Tlen =================
        // lane = g(2b) | ke(3b); rows (g, dl2), (g, dl2+8), k-eighth ke over concat
        const int ke  = lane >> 2;            // 0..7
        const int dl2 = wrp - 8;              // 0..7
        const int rsel = (ke >= 4);
        ull w2a[12], w2b[12];
        {
            const int ra = g * 64 + 16 * q + dl2;
            const int rb = ra + 8;
#pragma unroll
            for (int j = 0; j < 6; j++) {
                int k0 = ke * 4 + 32 * j;     // 4-float chunk, never straddles 128
                float4 fa, fb;
                if (k0 < 128) {
                    fa = *reinterpret_cast<const float4*>(w_ih2 + ra * 128 + k0);
                    fb = *reinterpret_cast<const float4*>(w_ih2 + rb * 128 + k0);
                } else {
                    fa = *reinterpret_cast<const float4*>(w_hh2 + ra * 64 + (k0 - 128));
                    fb = *reinterpret_cast<const float4*>(w_hh2 + rb * 64 + (k0 - 128));
                }
                w2a[2 * j] = pk(fa.x, fa.y); w2a[2 * j + 1] = pk(fa.z, fa.w);
                w2b[2 * j] = pk(fb.x, fb.y); w2b[2 * j + 1] = pk(fb.z, fb.w);
            }
        }
        float b2s[4];
#pragma unroll
        for (int j = 0; j < 4; j++) {
            int r = j * 64 + 16 * q + dl2 + (rsel ? 8 : 0);
            b2s[j] = b_ih2[r] + b_hh2[r];
        }
        const int dv2 = dl2 + (rsel ? 8 : 0);
        const uint32_t rQ = m0 + dd[ke & 3];  // 1 store/lane covers 4 ranks/row

        float c2 = 0.0f;
        int wW = 0, rR = 0, ph = 0;
        for (int i = 0; i <= Tlen; i++) {
            int bufR = 2;
            if (i >= 1) {
                mwait(base0 + MBO + rR * 8, (uint32_t)ph);
                bufR = rR;
                if (++rR == 3) { rR = 0; ph ^= 1; }
            }
            float h2v = 0.0f;
            if (i >= 1) {
                float s0[4], s1[4];
#pragma unroll
                for (int b = 0; b < 4; b++) {
                    const ulonglong2* hp =
                        reinterpret_cast<const ulonglong2*>(&sm.hc[bufR][b][0]);
                    ull a0 = 0ull, a1 = 0ull, b0 = 0ull, b1 = 0ull;
#pragma unroll
                    for (int j = 0; j < 6; j++) {
                        ulonglong2 h = hp[ke + 8 * j];   // 8 distinct addrs/warp
                        ffma2(a0, h.x, w2a[2 * j]);
                        ffma2(a1, h.y, w2a[2 * j + 1]);
                        ffma2(b0, h.x, w2b[2 * j]);
                        ffma2(b1, h.y, w2b[2 * j + 1]);
                    }
                    float2 f0 = u2f2(a0), f1 = u2f2(a1);
                    float2 f2 = u2f2(b0), f3 = u2f2(b1);
                    s0[b] = (f0.x + f0.y) + (f1.x + f1.y);
                    s1[b] = (f2.x + f2.y) + (f3.x + f3.y);
                }
#pragma unroll
                for (int b = 0; b < 4; b++) {
                    s0[b] += __shfl_xor_sync(FULL, s0[b], 4);
                    s1[b] += __shfl_xor_sync(FULL, s1[b], 4);
                    s0[b] += __shfl_xor_sync(FULL, s0[b], 8);
                    s1[b] += __shfl_xor_sync(FULL, s1[b], 8);
                    s0[b] += __shfl_xor_sync(FULL, s0[b], 16);
                    s1[b] += __shfl_xor_sync(FULL, s1[b], 16);
                }
                float sel[4];
#pragma unroll
                for (int b = 0; b < 4; b++) sel[b] = rsel ? s1[b] : s0[b];
                transpose4(sel, g);
                float ai = sel[0] + b2s[0];
                float af = sel[1] + b2s[1];
                float ag = sel[2] + b2s[2];
                float ao = sel[3] + b2s[3];
                c2 = sigm(af) * c2 + sigm(ai) * tanha(ag);
                h2v = sigm(ao) * tanha(c2);
            }
            const int beta = g;
            if (i == Tlen) {
                if ((ke & 3) == 0)
                    out[(4 * cid + beta) * 64 + 16 * q + dv2] = h2v;
            } else {
                st_cl(rQ + HCO + wW * HC_BUF_BYTES +
                      (beta * 196 + 128 + 16 * q + dv2) * 4, h2v);
                __syncwarp();
                if (lane == 0) {
                    fence_cluster();
                    uint32_t am = m0 + MBO + wW * 8;
                    marr(am); marr(am + dd[1]); marr(am + dd[2]); marr(am + dd[3]);
                }
                if (++wW == 3) wW = 0;
            }
        }
    }

    csync();  // keep smem alive for peers
}

extern "C" void kernel_launch(void* const* d_in, const int* in_sizes, int n_in,
                              void* d_out, int out_size) {
    const float* x     = (const float*)d_in[0];
    const float* w_ih1 = (const float*)d_in[1];
    const float* w_hh1 = (const float*)d_in[2];
    const float* b_ih1 = (const float*)d_in[3];
    const float* b_hh1 = (const float*)d_in[4];
    const float* w_ih2 = (const float*)d_in[5];
    const float* w_hh2 = (const float*)d_in[6];
    const float* b_ih2 = (const float*)d_in[7];
    const float* b_hh2 = (const float*)d_in[8];
    float* out = (float*)d_out;

    lstm_cluster_kernel<<<NCTA, NTHR>>>(
        x, w_ih1, w_hh1, b_ih1, b_hh1, w_ih2, w_hh2, b_ih2, b_hh2, out);
    (void)in_sizes; (void)n_in; (void)out_size;
}

// round 12
// speedup vs baseline: 1.2161x; 1.1187x over previous
#include <cuda_runtime.h>
#include <cstdint>

#define Tlen 1024
#define NCTA 128
#define NTHR 512

typedef unsigned long long ull;

#define TX_BYTES 3072   // per dest CTA per step: (128+64) dims x 4 batches x 4B

struct __align__(16) Smem {
    ull   mb[3];           // one tx-mbarrier per hc buffer (count=1 + expect_tx)
    ull   pad_;
    float hc[3][4][196];   // [buf][batch][h1(0..127) ++ h2(128..191)]
    float xs[1024][4];     // staged x, interleaved [t][b]
};
__shared__ Smem sm;

__device__ __forceinline__ float tanha(float x) {
    float y; asm("tanh.approx.f32 %0, %1;" : "=f"(y) : "f"(x)); return y;
}
__device__ __forceinline__ float sigm(float v) { return fmaf(tanha(0.5f * v), 0.5f, 0.5f); }

__device__ __forceinline__ uint32_t s2u(const void* p) {
    uint32_t a;
    asm("{ .reg .u64 t; cvta.to.shared.u64 t, %1; cvt.u32.u64 %0, t; }" : "=r"(a) : "l"(p));
    return a;
}
__device__ __forceinline__ uint32_t mapa_r(uint32_t saddr, int rank) {
    uint32_t r;
    asm volatile("mapa.shared::cluster.u32 %0, %1, %2;" : "=r"(r) : "r"(saddr), "r"(rank));
    return r;
}
// async remote store; on delivery, decrements tx-count of the mbar in the SAME dest CTA
__device__ __forceinline__ void st_async(uint32_t addr, float v, uint32_t mbar) {
    asm volatile(
        "st.async.shared::cluster.mbarrier::complete_tx::bytes.b32 [%0], %1, [%2];"
        :: "r"(addr), "r"(__float_as_uint(v)), "r"(mbar) : "memory");
}
__device__ __forceinline__ void arm_tx(uint32_t mbar, uint32_t bytes) {
    asm volatile("mbarrier.arrive.expect_tx.shared.b64 _, [%0], %1;"
                 :: "r"(mbar), "r"(bytes) : "memory");
}
__device__ __forceinline__ void mwait(uint32_t mbar, uint32_t parity) {
    asm volatile(
        "{\n\t.reg .pred P1;\n\t"
        "WAIT_LOOP_%=:\n\t"
        "mbarrier.try_wait.parity.acquire.cta.shared::cta.b64 P1, [%0], %1, 0x989680;\n\t"
        "@P1 bra.uni WAIT_DONE_%=;\n\t"
        "bra.uni WAIT_LOOP_%=;\n\t"
        "WAIT_DONE_%=:\n\t}"
        :: "r"(mbar), "r"(parity) : "memory");
}
__device__ __forceinline__ void csync() {
    asm volatile("barrier.cluster.arrive.aligned;" ::: "memory");
    asm volatile("barrier.cluster.wait.aligned;" ::: "memory");
}
__device__ __forceinline__ void ffma2(ull& acc, ull a, ull b) {
    asm("fma.rn.f32x2 %0, %1, %2, %0;" : "+l"(acc) : "l"(a), "l"(b));
}
__device__ __forceinline__ float2 u2f2(ull u) {
    float2 f;
    asm("mov.b64 {%0, %1}, %2;" : "=f"(f.x), "=f"(f.y) : "l"(u));
    return f;
}
__device__ __forceinline__ ull pk(float lo, float hi) {
    ull r;
    asm("mov.b64 %0, {%1, %2};" : "=l"(r) : "f"(lo), "f"(hi));
    return r;
}

// 4x4 gate<->batch transpose across lane bits [0:1]; lane G: in s[b]=M[G][b],
// out s[j]=M[j][G].
__device__ __forceinline__ void transpose4(float s[4], int G) {
    const unsigned FULL = 0xffffffffu;
    int g0 = G & 1, g1 = (G >> 1) & 1;
    float x0 = g0 ? s[0] : s[1];
    float x1 = g0 ? s[2] : s[3];
    float y0 = __shfl_xor_sync(FULL, x0, 1);
    float y1 = __shfl_xor_sync(FULL, x1, 1);
    if (g0) { s[0] = y0; s[2] = y1; } else { s[1] = y0; s[3] = y1; }
    x0 = g1 ? s[0] : s[2];
    x1 = g1 ? s[1] : s[3];
    y0 = __shfl_xor_sync(FULL, x0, 2);
    y1 = __shfl_xor_sync(FULL, x1, 2);
    if (g1) { s[0] = y0; s[1] = y1; } else { s[2] = y0; s[3] = y1; }
}

#define HC_BUF_BYTES (4 * 196 * 4)

__global__ void __launch_bounds__(NTHR, 1) __cluster_dims__(4, 1, 1)
lstm_cluster_kernel(
    const float* __restrict__ x,
    const float* __restrict__ w_ih1,  // [512][1]
    const float* __restrict__ w_hh1,  // [512][128]
    const float* __restrict__ b_ih1,
    const float* __restrict__ b_hh1,
    const float* __restrict__ w_ih2,  // [256][128]
    const float* __restrict__ w_hh2,  // [256][64]
    const float* __restrict__ b_ih2,
    const float* __restrict__ b_hh2,
    float* __restrict__ out)          // [128][64]
{
    const int tid  = threadIdx.x;
    const int lane = tid & 31;
    const int wrp  = tid >> 5;        // 16 warps: 0-7 = L1, 8-15 = L2
    const int q    = blockIdx.x & 3;
    const int cid  = blockIdx.x >> 2;
    const int g    = lane & 3;        // gate (batch after transpose)

    // ---------------- init smem ----------------
    for (int idx = tid; idx < 4 * 1024; idx += NTHR) {
        int b = idx >> 10, t = idx & 1023;
        sm.xs[t][b] = x[(4 * cid + b) * 1024 + t];
    }
    for (int idx = tid; idx < 3 * 4 * 196; idx += NTHR)
        (&sm.hc[0][0][0])[idx] = 0.0f;
    if (tid == 0) {
#pragma unroll
        for (int j = 0; j < 3; j++) {
            uint32_t a = s2u(&sm.mb[j]);
            asm volatile("mbarrier.init.shared.b64 [%0], 1;" :: "r"(a) : "memory");
            arm_tx(a, TX_BYTES);      // arm phase 0 of each buffer
        }
    }

    // ---------------- cluster address constants ----------------
    const uint32_t base0 = s2u(&sm);
    const uint32_t m0    = mapa_r(base0, 0);
    uint32_t dd[4];
    dd[0] = 0;
    dd[1] = mapa_r(base0, 1) - m0;
    dd[2] = mapa_r(base0, 2) - m0;
    dd[3] = mapa_r(base0, 3) - m0;
    const uint32_t HCO = s2u(&sm.hc[0][0][0]) - base0;
    const uint32_t MBO = s2u(&sm.mb[0]) - base0;

    csync();  // mbars (armed) + zeroed smem + xs visible cluster-wide

    const unsigned FULL = 0xffffffffu;

    if (wrp < 8) {
        // ================= L1 warps: steps 0..Tlen-1 =================
        // lane = g(2b) | kq(2b) | dlb(1b); rows (g, dl), (g, dl+16), k-quarter kq
        const int kq  = (lane >> 2) & 3;
        const int dlb = (lane >> 4) & 1;
        const int dl  = wrp * 2 + dlb;        // 0..15
        const int rsel = (kq >= 2);           // which row this lane finalizes
        ull w1a[16], w1b[16];
        {
            const int ra = g * 128 + 32 * q + dl;
            const float* pa = w_hh1 + ra * 128 + kq * 4;
            const float* pb = w_hh1 + (ra + 16) * 128 + kq * 4;
#pragma unroll
            for (int j = 0; j < 8; j++) {
                float4 fa = *reinterpret_cast<const float4*>(pa + j * 16);
                float4 fb = *reinterpret_cast<const float4*>(pb + j * 16);
                w1a[2 * j] = pk(fa.x, fa.y); w1a[2 * j + 1] = pk(fa.z, fa.w);
                w1b[2 * j] = pk(fb.x, fb.y); w1b[2 * j + 1] = pk(fb.z, fb.w);
            }
        }
        float wih1s[4], b1s[4];
#pragma unroll
        for (int j = 0; j < 4; j++) {
            int r = j * 128 + 32 * q + dl + (rsel ? 16 : 0);
            wih1s[j] = w_ih1[r];
            b1s[j]   = b_ih1[r] + b_hh1[r];
        }
        const int dv = dl + (rsel ? 16 : 0);
        const int rep = kq & 1;               // replica -> ranks {2rep, 2rep+1}
        const uint32_t rA = m0 + dd[2 * rep];
        const uint32_t rB = m0 + dd[2 * rep + 1];

        float c1 = 0.0f;
        int wW = 0, rR = 0, ph = 0;
        for (int i = 0; i < Tlen; i++) {
            int bufR;
            if (i == 0) bufR = 2;
            else {
                mwait(base0 + MBO + rR * 8, (uint32_t)ph);
                if (wrp == 0 && lane == 0)
                    arm_tx(base0 + MBO + rR * 8, TX_BYTES);  // re-arm next phase
                bufR = rR;
                if (++rR == 3) { rR = 0; ph ^= 1; }
            }
            float s0[4], s1[4];
#pragma unroll
            for (int b = 0; b < 4; b++) {
                const ulonglong2* hp =
                    reinterpret_cast<const ulonglong2*>(&sm.hc[bufR][b][0]);
                ull a0 = 0ull, a1 = 0ull, b0 = 0ull, b1 = 0ull;
#pragma unroll
                for (int j = 0; j < 8; j++) {
                    ulonglong2 h = hp[kq + 4 * j];   // 4 distinct addrs/warp
                    ffma2(a0, h.x, w1a[2 * j]);
                    ffma2(a1, h.y, w1a[2 * j + 1]);
                    ffma2(b0, h.x, w1b[2 * j]);
                    ffma2(b1, h.y, w1b[2 * j + 1]);
                }
                float2 f0 = u2f2(a0), f1 = u2f2(a1);
                float2 f2 = u2f2(b0), f3 = u2f2(b1);
                s0[b] = (f0.x + f0.y) + (f1.x + f1.y);
                s1[b] = (f2.x + f2.y) + (f3.x + f3.y);
            }
#pragma unroll
            for (int b = 0; b < 4; b++) {
                s0[b] += __shfl_xor_sync(FULL, s0[b], 4);
                s1[b] += __shfl_xor_sync(FULL, s1[b], 4);
                s0[b] += __shfl_xor_sync(FULL, s0[b], 8);
                s1[b] += __shfl_xor_sync(FULL, s1[b], 8);
            }
            float sel[4];
#pragma unroll
            for (int b = 0; b < 4; b++) sel[b] = rsel ? s1[b] : s0[b];
            transpose4(sel, g);
            const int beta = g;
            float xv = sm.xs[i][beta];
            float ai = fmaf(xv, wih1s[0], sel[0] + b1s[0]);
            float af = fmaf(xv, wih1s[1], sel[1] + b1s[1]);
            float ag = fmaf(xv, wih1s[2], sel[2] + b1s[2]);
            float ao = fmaf(xv, wih1s[3], sel[3] + b1s[3]);
            c1 = sigm(af) * c1 + sigm(ai) * tanha(ag);
            float h = sigm(ao) * tanha(c1);
            uint32_t off  = HCO + wW * HC_BUF_BYTES + (beta * 196 + 32 * q + dv) * 4;
            uint32_t mbof = MBO + wW * 8;
            st_async(rA + off, h, rA + mbof);
            st_async(rB + off, h, rB + mbof);
            if (++wW == 3) wW = 0;
        }
    } else {
        // ================= L2 warps: steps 0..Tlen =================
        // lane = g(2b) | ke(3b); rows (g, dl2), (g, dl2+8), k-eighth ke over concat
        const int ke  = lane >> 2;            // 0..7
        const int dl2 = wrp - 8;              // 0..7
        const int rsel = (ke >= 4);
        ull w2a[12], w2b[12];
        {
            const int ra = g * 64 + 16 * q + dl2;
            const int rb = ra + 8;
#pragma unroll
            for (int j = 0; j < 6; j++) {
                int k0 = ke * 4 + 32 * j;     // 4-float chunk, never straddles 128
                float4 fa, fb;
                if (k0 < 128) {
                    fa = *reinterpret_cast<const float4*>(w_ih2 + ra * 128 + k0);
                    fb = *reinterpret_cast<const float4*>(w_ih2 + rb * 128 + k0);
                } else {
                    fa = *reinterpret_cast<const float4*>(w_hh2 + ra * 64 + (k0 - 128));
                    fb = *reinterpret_cast<const float4*>(w_hh2 + rb * 64 + (k0 - 128));
                }
                w2a[2 * j] = pk(fa.x, fa.y); w2a[2 * j + 1] = pk(fa.z, fa.w);
                w2b[2 * j] = pk(fb.x, fb.y); w2b[2 * j + 1] = pk(fb.z, fb.w);
            }
        }
        float b2s[4];
#pragma unroll
        for (int j = 0; j < 4; j++) {
            int r = j * 64 + 16 * q + dl2 + (rsel ? 8 : 0);
            b2s[j] = b_ih2[r] + b_hh2[r];
        }
        const int dv2 = dl2 + (rsel ? 8 : 0);
        const uint32_t rQ = m0 + dd[ke & 3];  // 1 store/lane covers 4 ranks/row

        float c2 = 0.0f;
        int wW = 0, rR = 0, ph = 0;
        for (int i = 0; i <= Tlen; i++) {
            int bufR = 2;
            if (i >= 1) {
                mwait(base0 + MBO + rR * 8, (uint32_t)ph);
                bufR = rR;
                if (++rR == 3) { rR = 0; ph ^= 1; }
            }
            float h2v = 0.0f;
            if (i >= 1) {
                float s0[4], s1[4];
#pragma unroll
                for (int b = 0; b < 4; b++) {
                    const ulonglong2* hp =
                        reinterpret_cast<const ulonglong2*>(&sm.hc[bufR][b][0]);
                    ull a0 = 0ull, a1 = 0ull, b0 = 0ull, b1 = 0ull;
#pragma unroll
                    for (int j = 0; j < 6; j++) {
                        ulonglong2 h = hp[ke + 8 * j];   // 8 distinct addrs/warp
                        ffma2(a0, h.x, w2a[2 * j]);
                        ffma2(a1, h.y, w2a[2 * j + 1]);
                        ffma2(b0, h.x, w2b[2 * j]);
                        ffma2(b1, h.y, w2b[2 * j + 1]);
                    }
                    float2 f0 = u2f2(a0), f1 = u2f2(a1);
                    float2 f2 = u2f2(b0), f3 = u2f2(b1);
                    s0[b] = (f0.x + f0.y) + (f1.x + f1.y);
                    s1[b] = (f2.x + f2.y) + (f3.x + f3.y);
                }
#pragma unroll
                for (int b = 0; b < 4; b++) {
                    s0[b] += __shfl_xor_sync(FULL, s0[b], 4);
                    s1[b] += __shfl_xor_sync(FULL, s1[b], 4);
                    s0[b] += __shfl_xor_sync(FULL, s0[b], 8);
                    s1[b] += __shfl_xor_sync(FULL, s1[b], 8);
                    s0[b] += __shfl_xor_sync(FULL, s0[b], 16);
                    s1[b] += __shfl_xor_sync(FULL, s1[b], 16);
                }
                float sel[4];
#pragma unroll
                for (int b = 0; b < 4; b++) sel[b] = rsel ? s1[b] : s0[b];
                transpose4(sel, g);
                float ai = sel[0] + b2s[0];
                float af = sel[1] + b2s[1];
                float ag = sel[2] + b2s[2];
                float ao = sel[3] + b2s[3];
                c2 = sigm(af) * c2 + sigm(ai) * tanha(ag);
                h2v = sigm(ao) * tanha(c2);
            }
            const int beta = g;
            if (i == Tlen) {
                if ((ke & 3) == 0)
                    out[(4 * cid + beta) * 64 + 16 * q + dv2] = h2v;
            } else {
                uint32_t off  = HCO + wW * HC_BUF_BYTES +
                                (beta * 196 + 128 + 16 * q + dv2) * 4;
                st_async(rQ + off, h2v, rQ + MBO + wW * 8);
                if (++wW == 3) wW = 0;
            }
        }
    }

    csync();  // keep smem alive for peers
}

extern "C" void kernel_launch(void* const* d_in, const int* in_sizes, int n_in,
                              void* d_out, int out_size) {
    const float* x     = (const float*)d_in[0];
    const float* w_ih1 = (const float*)d_in[1];
    const float* w_hh1 = (const float*)d_in[2];
    const float* b_ih1 = (const float*)d_in[3];
    const float* b_hh1 = (const float*)d_in[4];
    const float* w_ih2 = (const float*)d_in[5];
    const float* w_hh2 = (const float*)d_in[6];
    const float* b_ih2 = (const float*)d_in[7];
    const float* b_hh2 = (const float*)d_in[8];
    float* out = (float*)d_out;

    lstm_cluster_kernel<<<NCTA, NTHR>>>(
        x, w_ih1, w_hh1, b_ih1, b_hh1, w_ih2, w_hh2, b_ih2, b_hh2, out);
    (void)in_sizes; (void)n_in; (void)out_size;
}

// round 13
// speedup vs baseline: 1.2202x; 1.0034x over previous
#include <cuda_runtime.h>
#include <cstdint>

#define Tlen 1024
#define NCTA 128
#define NTHR 512

typedef unsigned long long ull;

#define TX1 2048   // h1: 128 dims x 4 batches x 4B per dest CTA per step
#define TX2 1024   // h2:  64 dims x 4 batches x 4B per dest CTA per step

struct __align__(16) Smem {
    ull   mb1[4];          // h1 tx-barriers, one per buffer
    ull   mb2[4];          // h2 tx-barriers, one per buffer
    float hc[4][4][196];   // [buf][batch][h1(0..127) ++ h2(128..191)]
    float xs[1024][4];     // staged x, interleaved [t][b]
};
__shared__ Smem sm;

__device__ __forceinline__ float tanha(float x) {
    float y; asm("tanh.approx.f32 %0, %1;" : "=f"(y) : "f"(x)); return y;
}
__device__ __forceinline__ float sigm(float v) { return fmaf(tanha(0.5f * v), 0.5f, 0.5f); }

__device__ __forceinline__ uint32_t s2u(const void* p) {
    uint32_t a;
    asm("{ .reg .u64 t; cvta.to.shared.u64 t, %1; cvt.u32.u64 %0, t; }" : "=r"(a) : "l"(p));
    return a;
}
__device__ __forceinline__ uint32_t mapa_r(uint32_t saddr, int rank) {
    uint32_t r;
    asm volatile("mapa.shared::cluster.u32 %0, %1, %2;" : "=r"(r) : "r"(saddr), "r"(rank));
    return r;
}
// async remote store; on delivery decrements tx-count of the mbar in the dest CTA
__device__ __forceinline__ void st_async(uint32_t addr, float v, uint32_t mbar) {
    asm volatile(
        "st.async.shared::cluster.mbarrier::complete_tx::bytes.b32 [%0], %1, [%2];"
        :: "r"(addr), "r"(__float_as_uint(v)), "r"(mbar) : "memory");
}
__device__ __forceinline__ void arm_tx(uint32_t mbar, uint32_t bytes) {
    asm volatile("mbarrier.arrive.expect_tx.shared.b64 _, [%0], %1;"
                 :: "r"(mbar), "r"(bytes) : "memory");
}
__device__ __forceinline__ void mwait(uint32_t mbar, uint32_t parity) {
    asm volatile(
        "{\n\t.reg .pred P1;\n\t"
        "WAIT_LOOP_%=:\n\t"
        "mbarrier.try_wait.parity.acquire.cta.shared::cta.b64 P1, [%0], %1, 0x989680;\n\t"
        "@P1 bra.uni WAIT_DONE_%=;\n\t"
        "bra.uni WAIT_LOOP_%=;\n\t"
        "WAIT_DONE_%=:\n\t}"
        :: "r"(mbar), "r"(parity) : "memory");
}
__device__ __forceinline__ void csync() {
    asm volatile("barrier.cluster.arrive.aligned;" ::: "memory");
    asm volatile("barrier.cluster.wait.aligned;" ::: "memory");
}
__device__ __forceinline__ void ffma2(ull& acc, ull a, ull b) {
    asm("fma.rn.f32x2 %0, %1, %2, %0;" : "+l"(acc) : "l"(a), "l"(b));
}
__device__ __forceinline__ float2 u2f2(ull u) {
    float2 f;
    asm("mov.b64 {%0, %1}, %2;" : "=f"(f.x), "=f"(f.y) : "l"(u));
    return f;
}
__device__ __forceinline__ ull pk(float lo, float hi) {
    ull r;
    asm("mov.b64 %0, {%1, %2};" : "=l"(r) : "f"(lo), "f"(hi));
    return r;
}

// 4x4 gate<->batch transpose across lane bits [0:1]; lane G: in s[b]=M[G][b],
// out s[j]=M[j][G].
__device__ __forceinline__ void transpose4(float s[4], int G) {
    const unsigned FULL = 0xffffffffu;
    int g0 = G & 1, g1 = (G >> 1) & 1;
    float x0 = g0 ? s[0] : s[1];
    float x1 = g0 ? s[2] : s[3];
    float y0 = __shfl_xor_sync(FULL, x0, 1);
    float y1 = __shfl_xor_sync(FULL, x1, 1);
    if (g0) { s[0] = y0; s[2] = y1; } else { s[1] = y0; s[3] = y1; }
    x0 = g1 ? s[0] : s[2];
    x1 = g1 ? s[1] : s[3];
    y0 = __shfl_xor_sync(FULL, x0, 2);
    y1 = __shfl_xor_sync(FULL, x1, 2);
    if (g1) { s[0] = y0; s[1] = y1; } else { s[2] = y0; s[3] = y1; }
}

#define HC_BUF_BYTES (4 * 196 * 4)

__global__ void __launch_bounds__(NTHR, 1) __cluster_dims__(4, 1, 1)
lstm_cluster_kernel(
    const float* __restrict__ x,
    const float* __restrict__ w_ih1,  // [512][1]
    const float* __restrict__ w_hh1,  // [512][128]
    const float* __restrict__ b_ih1,
    const float* __restrict__ b_hh1,
    const float* __restrict__ w_ih2,  // [256][128]
    const float* __restrict__ w_hh2,  // [256][64]
    const float* __restrict__ b_ih2,
    const float* __restrict__ b_hh2,
    float* __restrict__ out)          // [128][64]
{
    const int tid  = threadIdx.x;
    const int lane = tid & 31;
    const int wrp  = tid >> 5;        // 16 warps: 0-7 = L1, 8-15 = L2
    const int q    = blockIdx.x & 3;
    const int cid  = blockIdx.x >> 2;
    const int g    = lane & 3;        // gate (batch after transpose)

    // ---------------- init smem ----------------
    for (int idx = tid; idx < 4 * 1024; idx += NTHR) {
        int b = idx >> 10, t = idx & 1023;
        sm.xs[t][b] = x[(4 * cid + b) * 1024 + t];
    }
    for (int idx = tid; idx < 4 * 4 * 196; idx += NTHR)
        (&sm.hc[0][0][0])[idx] = 0.0f;
    if (tid == 0) {
#pragma unroll
        for (int j = 0; j < 4; j++) {
            uint32_t a1 = s2u(&sm.mb1[j]);
            uint32_t a2 = s2u(&sm.mb2[j]);
            asm volatile("mbarrier.init.shared.b64 [%0], 1;" :: "r"(a1) : "memory");
            asm volatile("mbarrier.init.shared.b64 [%0], 1;" :: "r"(a2) : "memory");
            arm_tx(a1, TX1);
            arm_tx(a2, TX2);
        }
    }

    // ---------------- cluster address constants ----------------
    const uint32_t base0 = s2u(&sm);
    const uint32_t m0    = mapa_r(base0, 0);
    uint32_t dd[4];
    dd[0] = 0;
    dd[1] = mapa_r(base0, 1) - m0;
    dd[2] = mapa_r(base0, 2) - m0;
    dd[3] = mapa_r(base0, 3) - m0;
    const uint32_t HCO  = s2u(&sm.hc[0][0][0]) - base0;
    const uint32_t MB1O = s2u(&sm.mb1[0]) - base0;
    const uint32_t MB2O = s2u(&sm.mb2[0]) - base0;

    csync();  // armed mbars + zeroed smem + xs visible cluster-wide

    const unsigned FULL = 0xffffffffu;

    if (wrp < 8) {
        // ================= L1 warps: steps 0..Tlen-1 =================
        const int kq  = (lane >> 2) & 3;
        const int dlb = (lane >> 4) & 1;
        const int dl  = wrp * 2 + dlb;        // 0..15
        const int rsel = (kq >= 2);
        ull w1a[16], w1b[16];
        {
            const int ra = g * 128 + 32 * q + dl;
            const float* pa = w_hh1 + ra * 128 + kq * 4;
            const float* pb = w_hh1 + (ra + 16) * 128 + kq * 4;
#pragma unroll
            for (int j = 0; j < 8; j++) {
                float4 fa = *reinterpret_cast<const float4*>(pa + j * 16);
                float4 fb = *reinterpret_cast<const float4*>(pb + j * 16);
                w1a[2 * j] = pk(fa.x, fa.y); w1a[2 * j + 1] = pk(fa.z, fa.w);
                w1b[2 * j] = pk(fb.x, fb.y); w1b[2 * j + 1] = pk(fb.z, fb.w);
            }
        }
        float wih1s[4], b1s[4];
#pragma unroll
        for (int j = 0; j < 4; j++) {
            int r = j * 128 + 32 * q + dl + (rsel ? 16 : 0);
            wih1s[j] = w_ih1[r];
            b1s[j]   = b_ih1[r] + b_hh1[r];
        }
        const int dv = dl + (rsel ? 16 : 0);
        const int rep = kq & 1;               // replica -> ranks {2rep, 2rep+1}
        const uint32_t rA = m0 + dd[2 * rep];
        const uint32_t rB = m0 + dd[2 * rep + 1];

        float c1 = 0.0f;
        for (int i = 0; i < Tlen; i++) {
            int bufR = 3;                     // zeroed buffer for i==0
            if (i >= 1) {
                const int s = i - 1;
                bufR = s & 3;
                mwait(base0 + MB1O + bufR * 8, (uint32_t)((s >> 2) & 1));
                if (tid == 0)
                    arm_tx(base0 + MB1O + bufR * 8, TX1);  // re-arm next phase
            }
            if (i >= 4) {                     // ring safety: L2 done reading buf i-4
                const int s = i - 3;
                mwait(base0 + MB2O + (s & 3) * 8, (uint32_t)((s >> 2) & 1));
            }
            float s0[4], s1[4];
#pragma unroll
            for (int b = 0; b < 4; b++) {
                const ulonglong2* hp =
                    reinterpret_cast<const ulonglong2*>(&sm.hc[bufR][b][0]);
                ull a0 = 0ull, a1 = 0ull, b0 = 0ull, b1 = 0ull;
#pragma unroll
                for (int j = 0; j < 8; j++) {
                    ulonglong2 h = hp[kq + 4 * j];   // 4 distinct addrs/warp
                    ffma2(a0, h.x, w1a[2 * j]);
                    ffma2(a1, h.y, w1a[2 * j + 1]);
                    ffma2(b0, h.x, w1b[2 * j]);
                    ffma2(b1, h.y, w1b[2 * j + 1]);
                }
                float2 f0 = u2f2(a0), f1 = u2f2(a1);
                float2 f2 = u2f2(b0), f3 = u2f2(b1);
                s0[b] = (f0.x + f0.y) + (f1.x + f1.y);
                s1[b] = (f2.x + f2.y) + (f3.x + f3.y);
            }
#pragma unroll
            for (int b = 0; b < 4; b++) {
                s0[b] += __shfl_xor_sync(FULL, s0[b], 4);
                s1[b] += __shfl_xor_sync(FULL, s1[b], 4);
                s0[b] += __shfl_xor_sync(FULL, s0[b], 8);
                s1[b] += __shfl_xor_sync(FULL, s1[b], 8);
            }
            float sel[4];
#pragma unroll
            for (int b = 0; b < 4; b++) sel[b] = rsel ? s1[b] : s0[b];
            transpose4(sel, g);
            const int beta = g;
            float xv = sm.xs[i][beta];
            float ai = fmaf(xv, wih1s[0], sel[0] + b1s[0]);
            float af = fmaf(xv, wih1s[1], sel[1] + b1s[1]);
            float ag = fmaf(xv, wih1s[2], sel[2] + b1s[2]);
            float ao = fmaf(xv, wih1s[3], sel[3] + b1s[3]);
            c1 = sigm(af) * c1 + sigm(ai) * tanha(ag);
            float h = sigm(ao) * tanha(c1);
            const int bufW = i & 3;
            uint32_t off  = HCO + bufW * HC_BUF_BYTES + (beta * 196 + 32 * q + dv) * 4;
            uint32_t mbof = MB1O + bufW * 8;
            st_async(rA + off, h, rA + mbof);
            st_async(rB + off, h, rB + mbof);
        }
    } else {
        // ================= L2 warps: steps 0..Tlen =================
        const int ke  = lane >> 2;            // 0..7
        const int dl2 = wrp - 8;              // 0..7
        const int rsel = (ke >= 4);
        ull w2a[12], w2b[12];
        {
            const int ra = g * 64 + 16 * q + dl2;
            const int rb = ra + 8;
#pragma unroll
            for (int j = 0; j < 6; j++) {
                int k0 = ke * 4 + 32 * j;     // 4-float chunk, never straddles 128
                float4 fa, fb;
                if (k0 < 128) {
                    fa = *reinterpret_cast<const float4*>(w_ih2 + ra * 128 + k0);
                    fb = *reinterpret_cast<const float4*>(w_ih2 + rb * 128 + k0);
                } else {
                    fa = *reinterpret_cast<const float4*>(w_hh2 + ra * 64 + (k0 - 128));
                    fb = *reinterpret_cast<const float4*>(w_hh2 + rb * 64 + (k0 - 128));
                }
                w2a[2 * j] = pk(fa.x, fa.y); w2a[2 * j + 1] = pk(fa.z, fa.w);
                w2b[2 * j] = pk(fb.x, fb.y); w2b[2 * j + 1] = pk(fb.z, fb.w);
            }
        }
        float b2s[4];
#pragma unroll
        for (int j = 0; j < 4; j++) {
            int r = j * 64 + 16 * q + dl2 + (rsel ? 8 : 0);
            b2s[j] = b_ih2[r] + b_hh2[r];
        }
        const int dv2 = dl2 + (rsel ? 8 : 0);
        const uint32_t rQ = m0 + dd[ke & 3];  // 1 store/lane covers 4 ranks/row

        float c2 = 0.0f;
        for (int i = 0; i <= Tlen; i++) {
            float h2v = 0.0f;
            if (i >= 1) {
                const int s = i - 1;
                const int bufR = s & 3;
                const uint32_t par = (uint32_t)((s >> 2) & 1);
                mwait(base0 + MB1O + bufR * 8, par);   // h1(i-1)
                mwait(base0 + MB2O + bufR * 8, par);   // h2(i-2)
                if (tid == 256)
                    arm_tx(base0 + MB2O + bufR * 8, TX2);  // re-arm next phase
                float s0[4], s1[4];
#pragma unroll
                for (int b = 0; b < 4; b++) {
                    const ulonglong2* hp =
                        reinterpret_cast<const ulonglong2*>(&sm.hc[bufR][b][0]);
                    ull a0 = 0ull, a1 = 0ull, b0 = 0ull, b1 = 0ull;
#pragma unroll
                    for (int j = 0; j < 6; j++) {
                        ulonglong2 h = hp[ke + 8 * j];   // 8 distinct addrs/warp
                        ffma2(a0, h.x, w2a[2 * j]);
                        ffma2(a1, h.y, w2a[2 * j + 1]);
                        ffma2(b0, h.x, w2b[2 * j]);
                        ffma2(b1, h.y, w2b[2 * j + 1]);
                    }
                    float2 f0 = u2f2(a0), f1 = u2f2(a1);
                    float2 f2 = u2f2(b0), f3 = u2f2(b1);
                    s0[b] = (f0.x + f0.y) + (f1.x + f1.y);
                    s1[b] = (f2.x + f2.y) + (f3.x + f3.y);
                }
#pragma unroll
                for (int b = 0; b < 4; b++) {
                    s0[b] += __shfl_xor_sync(FULL, s0[b], 4);
                    s1[b] += __shfl_xor_sync(FULL, s1[b], 4);
                    s0[b] += __shfl_xor_sync(FULL, s0[b], 8);
                    s1[b] += __shfl_xor_sync(FULL, s1[b], 8);
                    s0[b] += __shfl_xor_sync(FULL, s0[b], 16);
                    s1[b] += __shfl_xor_sync(FULL, s1[b], 16);
                }
                float sel[4];
#pragma unroll
                for (int b = 0; b < 4; b++) sel[b] = rsel ? s1[b] : s0[b];
                transpose4(sel, g);
                float ai = sel[0] + b2s[0];
                float af = sel[1] + b2s[1];
                float ag = sel[2] + b2s[2];
                float ao = sel[3] + b2s[3];
                c2 = sigm(af) * c2 + sigm(ai) * tanha(ag);
                h2v = sigm(ao) * tanha(c2);
            }
            const int beta = g;
            if (i == Tlen) {
                if ((ke & 3) == 0)
                    out[(4 * cid + beta) * 64 + 16 * q + dv2] = h2v;
            } else {
                const int bufW = i & 3;
                uint32_t off = HCO + bufW * HC_BUF_BYTES +
                               (beta * 196 + 128 + 16 * q + dv2) * 4;
                st_async(rQ + off, h2v, rQ + MB2O + bufW * 8);
            }
        }
    }

    csync();  // keep smem alive for peers
}

extern "C" void kernel_launch(void* const* d_in, const int* in_sizes, int n_in,
                              void* d_out, int out_size) {
    const float* x     = (const float*)d_in[0];
    const float* w_ih1 = (const float*)d_in[1];
    const float* w_hh1 = (const float*)d_in[2];
    const float* b_ih1 = (const float*)d_in[3];
    const float* b_hh1 = (const float*)d_in[4];
    const float* w_ih2 = (const float*)d_in[5];
    const float* w_hh2 = (const float*)d_in[6];
    const float* b_ih2 = (const float*)d_in[7];
    const float* b_hh2 = (const float*)d_in[8];
    float* out = (float*)d_out;

    lstm_cluster_kernel<<<NCTA, NTHR>>>(
        x, w_ih1, w_hh1, b_ih1, b_hh1, w_ih2, w_hh2, b_ih2, b_hh2, out);
    (void)in_sizes; (void)n_in; (void)out_size;
}